// round 6
// baseline (speedup 1.0000x reference)
#include <cuda_runtime.h>

#define ROWS 4096
#define COLS 6144
#define NTILES 512              // 6144 / 12 column-tiles per row
#define PHI_TILE_FULL 341       // tiles 0..340 fully below col 4096; tile 341 contributes only col 4094
#define THREADS 256
#define NWARPS (THREADS / 32)

#define NLEAF 64                // 4096 = 64 leaves x 64 arrivals
#define LEAF_QUOTA (ROWS / NLEAF)
#define LEAF_STRIDE 32          // 32 uints = 128B between leaf counters (distinct L2 lines)

// Scratch partials (no allocation allowed in kernel_launch)
__device__ float g_r[1366];                          // rows 0,3,...,4095
__device__ float g_t[1365];                          // rows 1,4,...,4093
__device__ float g_phi[ROWS];                        // every row
__device__ unsigned int g_leaf[NLEAF * LEAF_STRIDE]; // leaf arrival counters (zero-init)
__device__ unsigned int g_root = 0;                  // root arrival counter

__device__ __forceinline__ float sigmoidf(float x) {
    return __fdividef(1.0f, 1.0f + __expf(-x));
}
__device__ __forceinline__ float circd(float ad) {   // ad = |s - t|, s,t in (0,1)
    return fminf(ad, 1.0f - ad);
}
__device__ __forceinline__ unsigned int atom_acqrel_add(unsigned int* p) {
    unsigned int prev;
    asm volatile("atom.acq_rel.gpu.global.add.u32 %0, [%1], 1;"
                 : "=r"(prev) : "l"(p) : "memory");
    return prev;
}

__global__ void __launch_bounds__(THREADS)
spherical_fused(const float* __restrict__ preds, const float* __restrict__ targs,
                float* __restrict__ out) {
    const int r = blockIdx.x;
    const int rowmod = r % 3;
    const bool wantRT = (rowmod < 2);
    const float4* __restrict__ p4 = (const float4*)(preds + (size_t)r * COLS);
    const float4* __restrict__ t4 = (const float4*)(targs + (size_t)r * COLS);

    const int ntiles = wantRT ? NTILES : (PHI_TILE_FULL + 1);

    float srt = 0.0f, sphi = 0.0f;

    for (int k = threadIdx.x; k < ntiles; k += THREADS) {
        const int i0 = 3 * k;
        float4 pa = p4[i0],     ta = t4[i0];
        float4 pb = p4[i0 + 1], tb = t4[i0 + 1];
        float4 pc = p4[i0 + 2], tc = t4[i0 + 2];

        float a0 = fabsf(sigmoidf(pa.x) - ta.x);
        float a1 = fabsf(sigmoidf(pa.y) - ta.y);
        float a2 = fabsf(sigmoidf(pa.z) - ta.z);   // col 12k+2  (phi if k<=341)
        float a3 = fabsf(sigmoidf(pa.w) - ta.w);
        float b0 = fabsf(sigmoidf(pb.x) - tb.x);
        float b1 = fabsf(sigmoidf(pb.y) - tb.y);   // col 12k+5  (phi if k<341)
        float b2 = fabsf(sigmoidf(pb.z) - tb.z);
        float b3 = fabsf(sigmoidf(pb.w) - tb.w);
        float c0 = fabsf(sigmoidf(pc.x) - tc.x);   // col 12k+8  (phi if k<341)
        float c1 = fabsf(sigmoidf(pc.y) - tc.y);
        float c2 = fabsf(sigmoidf(pc.z) - tc.z);
        float c3 = fabsf(sigmoidf(pc.w) - tc.w);   // col 12k+11 (phi if k<341)

        if (wantRT)
            srt += ((a0 + a1) + (a2 + a3)) + ((b0 + b1) + (b2 + b3)) + ((c0 + c1) + (c2 + c3));

        if (k <= PHI_TILE_FULL) {
            float ph = circd(a2);
            if (k < PHI_TILE_FULL)
                ph += circd(b1) + circd(c0) + circd(c3);
            sphi += ph;
        }
    }

    // Block reduction (deterministic tree)
    __shared__ float shA[NWARPS], shB[NWARPS];
#pragma unroll
    for (int o = 16; o > 0; o >>= 1) {
        srt  += __shfl_down_sync(0xFFFFFFFFu, srt,  o);
        sphi += __shfl_down_sync(0xFFFFFFFFu, sphi, o);
    }
    const int lane = threadIdx.x & 31;
    const int warp = threadIdx.x >> 5;
    if (lane == 0) { shA[warp] = srt; shB[warp] = sphi; }
    __syncthreads();

    __shared__ bool s_last;
    if (threadIdx.x == 0) {
        float a = shA[0], b = shB[0];
#pragma unroll
        for (int w = 1; w < NWARPS; w++) { a += shA[w]; b += shB[w]; }

        // Publish partials (plain stores), then release-ordered arrival.
        if (rowmod == 0)      g_r[r / 3] = a;
        else if (rowmod == 1) g_t[r / 3] = a;
        g_phi[r] = b;

        // Hierarchical arrival: 64 leaves (distinct L2 lines) -> 1 root.
        bool last = false;
        unsigned int lprev = atom_acqrel_add(&g_leaf[(r & (NLEAF - 1)) * LEAF_STRIDE]);
        if (lprev == (unsigned int)(LEAF_QUOTA - 1)) {
            unsigned int rprev = atom_acqrel_add(&g_root);
            last = (rprev == (unsigned int)(NLEAF - 1));
        }
        s_last = last;
    }
    __syncthreads();

    if (!s_last) return;

    // ---- Last-arriving block finalizes; fixed read/sum order => deterministic ----
    float rs = 0.0f, ts = 0.0f, ps = 0.0f;
    for (int i = threadIdx.x; i < 1366; i += THREADS) rs += __ldcg(&g_r[i]);
    for (int i = threadIdx.x; i < 1365; i += THREADS) ts += __ldcg(&g_t[i]);
    const float4* phi4 = (const float4*)g_phi;
    for (int i = threadIdx.x; i < ROWS / 4; i += THREADS) {
        float4 v = __ldcg(&phi4[i]);
        ps += (v.x + v.y) + (v.z + v.w);
    }

    // Reset counters for the next graph replay (spread across threads).
    if (threadIdx.x < NLEAF) g_leaf[threadIdx.x * LEAF_STRIDE] = 0;
    if (threadIdx.x == 0)    g_root = 0;

    __shared__ float sh3[3][NWARPS];
#pragma unroll
    for (int o = 16; o > 0; o >>= 1) {
        rs += __shfl_down_sync(0xFFFFFFFFu, rs, o);
        ts += __shfl_down_sync(0xFFFFFFFFu, ts, o);
        ps += __shfl_down_sync(0xFFFFFFFFu, ps, o);
    }
    if (lane == 0) { sh3[0][warp] = rs; sh3[1][warp] = ts; sh3[2][warp] = ps; }
    __syncthreads();
    if (warp == 0) {
        rs = (lane < NWARPS) ? sh3[0][lane] : 0.0f;
        ts = (lane < NWARPS) ? sh3[1][lane] : 0.0f;
        ps = (lane < NWARPS) ? sh3[2][lane] : 0.0f;
#pragma unroll
        for (int o = NWARPS / 2; o > 0; o >>= 1) {
            rs += __shfl_down_sync(0xFFFFFFFFu, rs, o);
            ts += __shfl_down_sync(0xFFFFFFFFu, ts, o);
            ps += __shfl_down_sync(0xFFFFFFFFu, ps, o);
        }
        if (lane == 0) {
            float r_loss   = rs / (1366.0f * 6144.0f);
            float t_loss   = ts / (1365.0f * 6144.0f);
            float phi_loss = ps / (4096.0f * 2048.0f);
            out[0] = r_loss + t_loss + phi_loss;
            out[1] = r_loss;
            out[2] = t_loss;
            out[3] = phi_loss;
        }
    }
}

extern "C" void kernel_launch(void* const* d_in, const int* in_sizes, int n_in,
                              void* d_out, int out_size) {
    const float* preds = (const float*)d_in[0];
    const float* targs = (const float*)d_in[1];
    float* out = (float*)d_out;
    (void)in_sizes; (void)n_in; (void)out_size;

    spherical_fused<<<ROWS, THREADS>>>(preds, targs, out);
}

// round 7
// speedup vs baseline: 1.1837x; 1.1837x over previous
#include <cuda_runtime.h>
#include <cuda_device_runtime_api.h>

#define ROWS 4096
#define COLS 6144
#define NTILES 512              // 6144 / 12 column-tiles per row
#define PHI_TILE_FULL 341       // tiles 0..340 fully below col 4096; tile 341 contributes only col 4094
#define THREADS 256
#define NWARPS (THREADS / 32)

#define FTHREADS 1024
#define FWARPS (FTHREADS / 32)

// Scratch partials (no allocation allowed in kernel_launch)
__device__ float g_r[1368];     // rows 0,3,...,4095 (1366 used, padded for float4)
__device__ float g_t[1368];     // rows 1,4,...,4093 (1365 used, padded)
__device__ float g_phi[ROWS];   // every row

__device__ __forceinline__ float sigmoidf(float x) {
    return __fdividef(1.0f, 1.0f + __expf(-x));
}
__device__ __forceinline__ float circd(float ad) {   // ad = |s - t|, s,t in (0,1)
    return fminf(ad, 1.0f - ad);
}

__global__ void __launch_bounds__(THREADS)
spherical_pass1(const float* __restrict__ preds, const float* __restrict__ targs) {
    const int r = blockIdx.x;
    const int rowmod = r % 3;
    const bool wantRT = (rowmod < 2);
    const float4* __restrict__ p4 = (const float4*)(preds + (size_t)r * COLS);
    const float4* __restrict__ t4 = (const float4*)(targs + (size_t)r * COLS);

    const int ntiles = wantRT ? NTILES : (PHI_TILE_FULL + 1);

    float srt = 0.0f, sphi = 0.0f;

    for (int k = threadIdx.x; k < ntiles; k += THREADS) {
        const int i0 = 3 * k;
        float4 pa = p4[i0],     ta = t4[i0];
        float4 pb = p4[i0 + 1], tb = t4[i0 + 1];
        float4 pc = p4[i0 + 2], tc = t4[i0 + 2];

        float a0 = fabsf(sigmoidf(pa.x) - ta.x);
        float a1 = fabsf(sigmoidf(pa.y) - ta.y);
        float a2 = fabsf(sigmoidf(pa.z) - ta.z);   // col 12k+2  (phi if k<=341)
        float a3 = fabsf(sigmoidf(pa.w) - ta.w);
        float b0 = fabsf(sigmoidf(pb.x) - tb.x);
        float b1 = fabsf(sigmoidf(pb.y) - tb.y);   // col 12k+5  (phi if k<341)
        float b2 = fabsf(sigmoidf(pb.z) - tb.z);
        float b3 = fabsf(sigmoidf(pb.w) - tb.w);
        float c0 = fabsf(sigmoidf(pc.x) - tc.x);   // col 12k+8  (phi if k<341)
        float c1 = fabsf(sigmoidf(pc.y) - tc.y);
        float c2 = fabsf(sigmoidf(pc.z) - tc.z);
        float c3 = fabsf(sigmoidf(pc.w) - tc.w);   // col 12k+11 (phi if k<341)

        if (wantRT)
            srt += ((a0 + a1) + (a2 + a3)) + ((b0 + b1) + (b2 + b3)) + ((c0 + c1) + (c2 + c3));

        if (k <= PHI_TILE_FULL) {
            float ph = circd(a2);
            if (k < PHI_TILE_FULL)
                ph += circd(b1) + circd(c0) + circd(c3);
            sphi += ph;
        }
    }

    // Allow the dependent pass2 launch to begin its setup while we drain.
    cudaTriggerProgrammaticLaunchCompletion();

    // Block reduction (deterministic tree)
    __shared__ float shA[NWARPS], shB[NWARPS];
#pragma unroll
    for (int o = 16; o > 0; o >>= 1) {
        srt  += __shfl_down_sync(0xFFFFFFFFu, srt,  o);
        sphi += __shfl_down_sync(0xFFFFFFFFu, sphi, o);
    }
    const int lane = threadIdx.x & 31;
    const int warp = threadIdx.x >> 5;
    if (lane == 0) { shA[warp] = srt; shB[warp] = sphi; }
    __syncthreads();

    if (threadIdx.x == 0) {
        float a = shA[0], b = shB[0];
#pragma unroll
        for (int w = 1; w < NWARPS; w++) { a += shA[w]; b += shB[w]; }
        if (rowmod == 0)      g_r[r / 3] = a;
        else if (rowmod == 1) g_t[r / 3] = a;
        g_phi[r] = b;
    }
}

__global__ void __launch_bounds__(FTHREADS)
spherical_pass2(float* __restrict__ out) {
    // Wait for pass1's grid (and its memory) to complete.
    cudaGridDependencySynchronize();

    // Zero the pad slots deterministically before reading? They are static
    // zero-initialized and never written by pass1 (indices 1366,1367 / 1365..1367),
    // so float4 reads over the padded arrays are safe and deterministic.
    float rs = 0.0f, ts = 0.0f, ps = 0.0f;
    const float4* r4   = (const float4*)g_r;      // 342 float4 (1368 floats)
    const float4* t4   = (const float4*)g_t;      // 342 float4
    const float4* phi4 = (const float4*)g_phi;    // 1024 float4

    // One strided iteration each (FTHREADS=1024 covers all counts in <=1 round)
    if (threadIdx.x < 342) {
        float4 v = __ldcg(&r4[threadIdx.x]);
        rs = (v.x + v.y) + (v.z + v.w);
        float4 w = __ldcg(&t4[threadIdx.x]);
        ts = (w.x + w.y) + (w.z + w.w);
    }
    {
        float4 v = __ldcg(&phi4[threadIdx.x]);
        ps = (v.x + v.y) + (v.z + v.w);
    }

    __shared__ float sh[3][FWARPS];
#pragma unroll
    for (int o = 16; o > 0; o >>= 1) {
        rs += __shfl_down_sync(0xFFFFFFFFu, rs, o);
        ts += __shfl_down_sync(0xFFFFFFFFu, ts, o);
        ps += __shfl_down_sync(0xFFFFFFFFu, ps, o);
    }
    const int lane = threadIdx.x & 31;
    const int warp = threadIdx.x >> 5;
    if (lane == 0) { sh[0][warp] = rs; sh[1][warp] = ts; sh[2][warp] = ps; }
    __syncthreads();
    if (warp == 0) {
        rs = (lane < FWARPS) ? sh[0][lane] : 0.0f;
        ts = (lane < FWARPS) ? sh[1][lane] : 0.0f;
        ps = (lane < FWARPS) ? sh[2][lane] : 0.0f;
#pragma unroll
        for (int o = 16; o > 0; o >>= 1) {
            rs += __shfl_down_sync(0xFFFFFFFFu, rs, o);
            ts += __shfl_down_sync(0xFFFFFFFFu, ts, o);
            ps += __shfl_down_sync(0xFFFFFFFFu, ps, o);
        }
        if (lane == 0) {
            float r_loss   = rs / (1366.0f * 6144.0f);
            float t_loss   = ts / (1365.0f * 6144.0f);
            float phi_loss = ps / (4096.0f * 2048.0f);
            out[0] = r_loss + t_loss + phi_loss;
            out[1] = r_loss;
            out[2] = t_loss;
            out[3] = phi_loss;
        }
    }
}

extern "C" void kernel_launch(void* const* d_in, const int* in_sizes, int n_in,
                              void* d_out, int out_size) {
    const float* preds = (const float*)d_in[0];
    const float* targs = (const float*)d_in[1];
    float* out = (float*)d_out;
    (void)in_sizes; (void)n_in; (void)out_size;

    spherical_pass1<<<ROWS, THREADS>>>(preds, targs);

    // pass2 via PDL: may begin setup before pass1 fully drains; it gates on
    // cudaGridDependencySynchronize() before touching pass1's outputs.
    cudaLaunchAttribute attrs[1];
    attrs[0].id = cudaLaunchAttributeProgrammaticStreamSerialization;
    attrs[0].val.programmaticStreamSerializationAllowed = 1;

    cudaLaunchConfig_t cfg = {};
    cfg.gridDim = dim3(1, 1, 1);
    cfg.blockDim = dim3(FTHREADS, 1, 1);
    cfg.dynamicSmemBytes = 0;
    cfg.stream = 0;
    cfg.attrs = attrs;
    cfg.numAttrs = 1;

    cudaLaunchKernelEx(&cfg, spherical_pass2, out);
}

// round 8
// speedup vs baseline: 1.2576x; 1.0624x over previous
#include <cuda_runtime.h>
#include <cuda_device_runtime_api.h>

#define ROWS 4096
#define COLS 6144
#define NTILES 512              // 6144 / 12 column-tiles per row
#define PHI_TILE_FULL 341       // tiles 0..340 fully below col 4096; tile 341 contributes only col 4094
#define THREADS 256
#define NWARPS (THREADS / 32)

#define FTHREADS 1024
#define FWARPS (FTHREADS / 32)

// Scratch partials (no allocation allowed in kernel_launch)
__device__ float g_r[1368];     // rows 0,3,...,4095 (1366 used, padded for float4)
__device__ float g_t[1368];     // rows 1,4,...,4093 (1365 used, padded)
__device__ float g_phi[ROWS];   // every row

// sigmoid(x) = 0.5*tanh(x/2) + 0.5 : one MUFU (TANH) + FMAs instead of EX2+RCP.
__device__ __forceinline__ float sigmoidf(float x) {
    float y;
    asm("tanh.approx.f32 %0, %1;" : "=f"(y) : "f"(0.5f * x));
    return fmaf(0.5f, y, 0.5f);
}
__device__ __forceinline__ float circd(float ad) {   // ad = |s - t|, s,t in (0,1)
    return fminf(ad, 1.0f - ad);
}

__global__ void __launch_bounds__(THREADS)
spherical_pass1(const float* __restrict__ preds, const float* __restrict__ targs) {
    const int r = blockIdx.x;
    const int rowmod = r % 3;
    const bool wantRT = (rowmod < 2);
    const float4* __restrict__ p4 = (const float4*)(preds + (size_t)r * COLS);
    const float4* __restrict__ t4 = (const float4*)(targs + (size_t)r * COLS);

    const int ntiles = wantRT ? NTILES : (PHI_TILE_FULL + 1);

    float srt = 0.0f, sphi = 0.0f;

    for (int k = threadIdx.x; k < ntiles; k += THREADS) {
        const int i0 = 3 * k;
        // Streaming loads: data is touched exactly once — evict-first policy.
        float4 pa = __ldcs(&p4[i0]),     ta = __ldcs(&t4[i0]);
        float4 pb = __ldcs(&p4[i0 + 1]), tb = __ldcs(&t4[i0 + 1]);
        float4 pc = __ldcs(&p4[i0 + 2]), tc = __ldcs(&t4[i0 + 2]);

        float a0 = fabsf(sigmoidf(pa.x) - ta.x);
        float a1 = fabsf(sigmoidf(pa.y) - ta.y);
        float a2 = fabsf(sigmoidf(pa.z) - ta.z);   // col 12k+2  (phi if k<=341)
        float a3 = fabsf(sigmoidf(pa.w) - ta.w);
        float b0 = fabsf(sigmoidf(pb.x) - tb.x);
        float b1 = fabsf(sigmoidf(pb.y) - tb.y);   // col 12k+5  (phi if k<341)
        float b2 = fabsf(sigmoidf(pb.z) - tb.z);
        float b3 = fabsf(sigmoidf(pb.w) - tb.w);
        float c0 = fabsf(sigmoidf(pc.x) - tc.x);   // col 12k+8  (phi if k<341)
        float c1 = fabsf(sigmoidf(pc.y) - tc.y);
        float c2 = fabsf(sigmoidf(pc.z) - tc.z);
        float c3 = fabsf(sigmoidf(pc.w) - tc.w);   // col 12k+11 (phi if k<341)

        if (wantRT)
            srt += ((a0 + a1) + (a2 + a3)) + ((b0 + b1) + (b2 + b3)) + ((c0 + c1) + (c2 + c3));

        if (k <= PHI_TILE_FULL) {
            float ph = circd(a2);
            if (k < PHI_TILE_FULL)
                ph += circd(b1) + circd(c0) + circd(c3);
            sphi += ph;
        }
    }

    // Allow the dependent pass2 launch to begin its setup while we drain.
    cudaTriggerProgrammaticLaunchCompletion();

    // Block reduction (deterministic tree)
    __shared__ float shA[NWARPS], shB[NWARPS];
#pragma unroll
    for (int o = 16; o > 0; o >>= 1) {
        srt  += __shfl_down_sync(0xFFFFFFFFu, srt,  o);
        sphi += __shfl_down_sync(0xFFFFFFFFu, sphi, o);
    }
    const int lane = threadIdx.x & 31;
    const int warp = threadIdx.x >> 5;
    if (lane == 0) { shA[warp] = srt; shB[warp] = sphi; }
    __syncthreads();

    if (threadIdx.x == 0) {
        float a = shA[0], b = shB[0];
#pragma unroll
        for (int w = 1; w < NWARPS; w++) { a += shA[w]; b += shB[w]; }
        if (rowmod == 0)      g_r[r / 3] = a;
        else if (rowmod == 1) g_t[r / 3] = a;
        g_phi[r] = b;
    }
}

__global__ void __launch_bounds__(FTHREADS)
spherical_pass2(float* __restrict__ out) {
    // Wait for pass1's grid (and its memory) to complete.
    cudaGridDependencySynchronize();

    float rs = 0.0f, ts = 0.0f, ps = 0.0f;
    const float4* r4   = (const float4*)g_r;      // 342 float4 (pad slots are never written: stay 0)
    const float4* t4   = (const float4*)g_t;      // 342 float4
    const float4* phi4 = (const float4*)g_phi;    // 1024 float4

    if (threadIdx.x < 342) {
        float4 v = __ldcg(&r4[threadIdx.x]);
        rs = (v.x + v.y) + (v.z + v.w);
        float4 w = __ldcg(&t4[threadIdx.x]);
        ts = (w.x + w.y) + (w.z + w.w);
    }
    {
        float4 v = __ldcg(&phi4[threadIdx.x]);
        ps = (v.x + v.y) + (v.z + v.w);
    }

    __shared__ float sh[3][FWARPS];
#pragma unroll
    for (int o = 16; o > 0; o >>= 1) {
        rs += __shfl_down_sync(0xFFFFFFFFu, rs, o);
        ts += __shfl_down_sync(0xFFFFFFFFu, ts, o);
        ps += __shfl_down_sync(0xFFFFFFFFu, ps, o);
    }
    const int lane = threadIdx.x & 31;
    const int warp = threadIdx.x >> 5;
    if (lane == 0) { sh[0][warp] = rs; sh[1][warp] = ts; sh[2][warp] = ps; }
    __syncthreads();
    if (warp == 0) {
        rs = (lane < FWARPS) ? sh[0][lane] : 0.0f;
        ts = (lane < FWARPS) ? sh[1][lane] : 0.0f;
        ps = (lane < FWARPS) ? sh[2][lane] : 0.0f;
#pragma unroll
        for (int o = 16; o > 0; o >>= 1) {
            rs += __shfl_down_sync(0xFFFFFFFFu, rs, o);
            ts += __shfl_down_sync(0xFFFFFFFFu, ts, o);
            ps += __shfl_down_sync(0xFFFFFFFFu, ps, o);
        }
        if (lane == 0) {
            float r_loss   = rs / (1366.0f * 6144.0f);
            float t_loss   = ts / (1365.0f * 6144.0f);
            float phi_loss = ps / (4096.0f * 2048.0f);
            out[0] = r_loss + t_loss + phi_loss;
            out[1] = r_loss;
            out[2] = t_loss;
            out[3] = phi_loss;
        }
    }
}

extern "C" void kernel_launch(void* const* d_in, const int* in_sizes, int n_in,
                              void* d_out, int out_size) {
    const float* preds = (const float*)d_in[0];
    const float* targs = (const float*)d_in[1];
    float* out = (float*)d_out;
    (void)in_sizes; (void)n_in; (void)out_size;

    spherical_pass1<<<ROWS, THREADS>>>(preds, targs);

    // pass2 via PDL: launch setup overlaps pass1's drain; gated by
    // cudaGridDependencySynchronize() before touching pass1's outputs.
    cudaLaunchAttribute attrs[1];
    attrs[0].id = cudaLaunchAttributeProgrammaticStreamSerialization;
    attrs[0].val.programmaticStreamSerializationAllowed = 1;

    cudaLaunchConfig_t cfg = {};
    cfg.gridDim = dim3(1, 1, 1);
    cfg.blockDim = dim3(FTHREADS, 1, 1);
    cfg.dynamicSmemBytes = 0;
    cfg.stream = 0;
    cfg.attrs = attrs;
    cfg.numAttrs = 1;

    cudaLaunchKernelEx(&cfg, spherical_pass2, out);
}